// round 1
// baseline (speedup 1.0000x reference)
#include <cuda_runtime.h>

#define NN 2048
#define DD 64

typedef unsigned long long ull;

// Scratch: A[i] = x_i @ W1[:64] + b1 ; B[j] = x_j @ W1[64:]
__device__ float g_A[NN * DD];
__device__ float g_B[NN * DD];

// ---------- packed f32x2 helpers (full-rate fp32 FMA on Blackwell) ----------
__device__ __forceinline__ ull pack2(float lo, float hi) {
    ull r; asm("mov.b64 %0, {%1, %2};" : "=l"(r) : "f"(lo), "f"(hi)); return r;
}
__device__ __forceinline__ void unpack2(ull v, float& lo, float& hi) {
    asm("mov.b64 {%0, %1}, %2;" : "=f"(lo), "=f"(hi) : "l"(v));
}
__device__ __forceinline__ void ffma2(ull& d, ull a, ull b) {
    asm("fma.rn.f32x2 %0, %1, %2, %0;" : "+l"(d) : "l"(a), "l"(b));
}
__device__ __forceinline__ void fadd2(ull& d, ull a) {
    asm("add.rn.f32x2 %0, %0, %1;" : "+l"(d) : "l"(a));
}

// ---------------- Kernel 1: precompute A and B rows ----------------
__global__ void precompute_kernel(const float* __restrict__ X,
                                  const float* __restrict__ W1,
                                  const float* __restrict__ b1) {
    __shared__ float xs[DD];
    const int i = blockIdx.x;
    const int d = threadIdx.x;
    xs[d] = X[i * DD + d];
    __syncthreads();
    float a = b1[d], b = 0.f;
#pragma unroll 8
    for (int k = 0; k < DD; k++) {
        const float xv = xs[k];
        a = fmaf(xv, __ldg(&W1[k * DD + d]), a);
        b = fmaf(xv, __ldg(&W1[(DD + k) * DD + d]), b);
    }
    g_A[i * DD + d] = a;
    g_B[i * DD + d] = b;
}

// ---------------- Kernel 2: main pair kernel ----------------
// Block = (one i) x (up to 128 j's). 256 threads.
// Phase A: stage h1 = relu(A[i]+B[j]) in SMEM (K split into 2 phases of 32).
// Phase B: SIMT GEMM h2 = relu(h1 @ W2 + b2)  (f32x2 accumulators).
// Phase C: heads out = h2 @ [We|Wt] + [be|bt]  (f32x2), packed-triu store.
__global__ __launch_bounds__(256) void edge_main(
    const float* __restrict__ W2, const float* __restrict__ b2,
    const float* __restrict__ We, const float* __restrict__ be,
    const float* __restrict__ Wt, const float* __restrict__ bt,
    float* __restrict__ out)
{
    const int i  = blockIdx.y;
    const int jt = blockIdx.x;
    int jlo = jt * 128; if (i + 1 > jlo) jlo = i + 1;
    int jhi = jt * 128 + 128; if (jhi > NN) jhi = NN;
    if (jlo >= jhi) return;
    const int cnt = jhi - jlo;

    // sbuf: phases A/B -> sH[128][36] (4608) + sW2[64][64] (4096) = 8704 floats
    //       phase  C   -> reused as h2buf[128][68] (8704 floats exactly)
    __shared__ __align__(16) float sbuf[8704];
    __shared__ __align__(16) float sW3s[64 * 16];  // [We | Wt | pad] pitch 16
    __shared__ __align__(16) float sA[64];
    __shared__ __align__(16) float sB2[64];
    __shared__ float sB3[16];
    __shared__ __align__(16) float sOut[128 * 9];

    float* sH  = sbuf;          // pitch 36
    float* sW2 = sbuf + 4608;   // 64x64

    const int tid = threadIdx.x;

    // ---- phase 1: stage weights ----
    for (int idx = tid; idx < 4096; idx += 256) sW2[idx] = W2[idx];
    for (int idx = tid; idx < 1024; idx += 256) {
        const int k = idx >> 4, c = idx & 15;
        float v = 0.f;
        if (c == 0) v = We[k];
        else if (c < 9) v = Wt[k * 8 + c - 1];
        sW3s[idx] = v;
    }
    if (tid < 64) { sA[tid] = g_A[i * 64 + tid]; sB2[tid] = b2[tid]; }
    if (tid < 16) sB3[tid] = (tid == 0) ? be[0] : (tid < 9 ? bt[tid - 1] : 0.f);
    __syncthreads();

    // ---- GEMM setup: 8 warps as 4(M) x 2(N); thread: 8 rows (stride 4) x 4 cols ----
    const int lane  = tid & 31;
    const int warp  = tid >> 5;
    const int warpM = warp & 3;
    const int warpN = warp >> 2;
    const int mRow0 = warpM * 32 + (lane & 3);     // rows mRow0 + 4*r
    const int nBase = warpN * 32 + (lane >> 2) * 4;

    ull acc[8][2];
#pragma unroll
    for (int r = 0; r < 8; r++) { acc[r][0] = 0ull; acc[r][1] = 0ull; }

    const float4* gB4 = (const float4*)g_B;
    const float4* sA4 = (const float4*)sA;

    for (int kph = 0; kph < 2; kph++) {
        // stage h1 columns [kph*32, kph*32+32)
        for (int idx = tid; idx < 128 * 8; idx += 256) {
            const int m = idx >> 3, kq = idx & 7;
            const int j = jlo + m;
            float4 v = make_float4(0.f, 0.f, 0.f, 0.f);
            if (j < jhi) {
                const float4 b4 = gB4[j * 16 + kph * 8 + kq];
                const float4 a4 = sA4[kph * 8 + kq];
                v.x = fmaxf(a4.x + b4.x, 0.f);
                v.y = fmaxf(a4.y + b4.y, 0.f);
                v.z = fmaxf(a4.z + b4.z, 0.f);
                v.w = fmaxf(a4.w + b4.w, 0.f);
            }
            *(float4*)(sH + m * 36 + kq * 4) = v;
        }
        __syncthreads();

        const float* sHrow = sH + mRow0 * 36;
        const float* w2p   = sW2 + kph * 32 * 64 + nBase;
#pragma unroll 4
        for (int kk = 0; kk < 32; kk++) {
            const ull* bp = (const ull*)(w2p + kk * 64);
            const ull b01 = bp[0];
            const ull b23 = bp[1];
#pragma unroll
            for (int r = 0; r < 8; r++) {
                const float a = sHrow[r * 4 * 36 + kk];
                const ull ad = pack2(a, a);
                ffma2(acc[r][0], ad, b01);
                ffma2(acc[r][1], ad, b23);
            }
        }
        __syncthreads();
    }

    // ---- h2 = relu(acc + b2) -> h2buf (pitch 68, overlays sH+sW2) ----
    float* h2buf = sbuf;
    const float4 bb = *(const float4*)(sB2 + nBase);
#pragma unroll
    for (int r = 0; r < 8; r++) {
        float x0, x1, x2, x3;
        unpack2(acc[r][0], x0, x1);
        unpack2(acc[r][1], x2, x3);
        float4 h;
        h.x = fmaxf(x0 + bb.x, 0.f);
        h.y = fmaxf(x1 + bb.y, 0.f);
        h.z = fmaxf(x2 + bb.z, 0.f);
        h.w = fmaxf(x3 + bb.w, 0.f);
        *(float4*)(h2buf + (mRow0 + r * 4) * 68 + nBase) = h;
    }
    __syncthreads();

    // ---- heads: 2 threads per row, K split 32/32, f32x2 ----
    {
        const int row = tid >> 1, half = tid & 1;
        const float* hrow = h2buf + row * 68 + half * 32;
        const ull* w3b = (const ull*)sW3s + half * 32 * 8;  // pitch 8 ull
        ull a9[5] = {0ull, 0ull, 0ull, 0ull, 0ull};
#pragma unroll 8
        for (int kk = 0; kk < 32; kk++) {
            const float v = hrow[kk];
            const ull vd = pack2(v, v);
            const ull* wr = w3b + kk * 8;
            ffma2(a9[0], vd, wr[0]);
            ffma2(a9[1], vd, wr[1]);
            ffma2(a9[2], vd, wr[2]);
            ffma2(a9[3], vd, wr[3]);
            ffma2(a9[4], vd, wr[4]);
        }
#pragma unroll
        for (int p = 0; p < 5; p++) {
            ull o = __shfl_xor_sync(0xffffffffu, a9[p], 1);
            fadd2(a9[p], o);
        }
        if (half == 0) {
            float v0, v1, v2, v3, v4, v5, v6, v7, v8, v9;
            unpack2(a9[0], v0, v1); unpack2(a9[1], v2, v3);
            unpack2(a9[2], v4, v5); unpack2(a9[3], v6, v7);
            unpack2(a9[4], v8, v9);
            float* dst = sOut + row * 9;
            dst[0] = v0 + sB3[0]; dst[1] = v1 + sB3[1]; dst[2] = v2 + sB3[2];
            dst[3] = v3 + sB3[3]; dst[4] = v4 + sB3[4]; dst[5] = v5 + sB3[5];
            dst[6] = v6 + sB3[6]; dst[7] = v7 + sB3[7]; dst[8] = v8 + sB3[8];
        }
    }
    __syncthreads();

    // ---- packed-triu contiguous store ----
    const size_t pair0 = (size_t)i * (2 * NN - i - 1) / 2 + (size_t)(jlo - i - 1);
    float* gdst = out + pair0 * 9;
    const int tot = cnt * 9;
    for (int idx = tid; idx < tot; idx += 256) gdst[idx] = sOut[idx];
}

extern "C" void kernel_launch(void* const* d_in, const int* in_sizes, int n_in,
                              void* d_out, int out_size) {
    (void)in_sizes; (void)n_in; (void)out_size;
    const float* X  = (const float*)d_in[0];
    const float* W1 = (const float*)d_in[1];
    const float* b1 = (const float*)d_in[2];
    const float* W2 = (const float*)d_in[3];
    const float* b2 = (const float*)d_in[4];
    const float* We = (const float*)d_in[5];
    const float* be = (const float*)d_in[6];
    const float* Wt = (const float*)d_in[7];
    const float* bt = (const float*)d_in[8];
    float* out = (float*)d_out;

    precompute_kernel<<<NN, DD>>>(X, W1, b1);

    dim3 grid(NN / 128, NN);
    edge_main<<<grid, 256>>>(W2, b2, We, be, Wt, bt, out);
}

// round 2
// speedup vs baseline: 1.0090x; 1.0090x over previous
#include <cuda_runtime.h>

#define NN 2048
#define DD 64

typedef unsigned long long ull;

// Scratch: A[i] = x_i @ W1[:64] + b1 ; B[j] = x_j @ W1[64:]
__device__ float g_A[NN * DD];
__device__ float g_B[NN * DD];

// ---------- packed f32x2 helpers (full-rate fp32 FMA on Blackwell) ----------
__device__ __forceinline__ ull pack2(float lo, float hi) {
    ull r; asm("mov.b64 %0, {%1, %2};" : "=l"(r) : "f"(lo), "f"(hi)); return r;
}
__device__ __forceinline__ void unpack2(ull v, float& lo, float& hi) {
    asm("mov.b64 {%0, %1}, %2;" : "=f"(lo), "=f"(hi) : "l"(v));
}
__device__ __forceinline__ void ffma2(ull& d, ull a, ull b) {
    asm("fma.rn.f32x2 %0, %1, %2, %0;" : "+l"(d) : "l"(a), "l"(b));
}
__device__ __forceinline__ void fadd2(ull& d, ull a) {
    asm("add.rn.f32x2 %0, %0, %1;" : "+l"(d) : "l"(a));
}

// ---------------- Kernel 1: precompute A and B rows ----------------
__global__ void precompute_kernel(const float* __restrict__ X,
                                  const float* __restrict__ W1,
                                  const float* __restrict__ b1) {
    __shared__ float xs[DD];
    const int i = blockIdx.x;
    const int d = threadIdx.x;
    xs[d] = X[i * DD + d];
    __syncthreads();
    float a = b1[d], b = 0.f;
#pragma unroll 8
    for (int k = 0; k < DD; k++) {
        const float xv = xs[k];
        a = fmaf(xv, __ldg(&W1[k * DD + d]), a);
        b = fmaf(xv, __ldg(&W1[(DD + k) * DD + d]), b);
    }
    g_A[i * DD + d] = a;
    g_B[i * DD + d] = b;
}

// ---------------- Kernel 2: main pair kernel ----------------
// Block = (one i) x (up to 128 j's). 256 threads.
// Phase A: stage h1 = relu(A[i]+B[j]) in SMEM (K split into 2 phases of 32).
// Phase B: SIMT GEMM h2 = relu(h1 @ W2 + b2)  (f32x2 accumulators,
//          A-operand fetched as LDS.128 over k-groups of 4).
// Phase C: heads out = h2 @ [We|Wt] + [be|bt]  (f32x2), packed-triu store.
__global__ __launch_bounds__(256, 2) void edge_main(
    const float* __restrict__ W2, const float* __restrict__ b2,
    const float* __restrict__ We, const float* __restrict__ be,
    const float* __restrict__ Wt, const float* __restrict__ bt,
    float* __restrict__ out)
{
    const int i  = blockIdx.y;
    const int jt = blockIdx.x;
    int jlo = jt * 128; if (i + 1 > jlo) jlo = i + 1;
    int jhi = jt * 128 + 128; if (jhi > NN) jhi = NN;
    if (jlo >= jhi) return;
    const int cnt = jhi - jlo;

    // sbuf: phases A/B -> sH[128][36] (4608) + sW2[64][64] (4096) = 8704 floats
    //       phase  C   -> reused as h2buf[128][68] (8704 floats exactly)
    __shared__ __align__(16) float sbuf[8704];
    __shared__ __align__(16) float sW3s[64 * 16];  // [We | Wt | pad] pitch 16
    __shared__ __align__(16) float sA[64];
    __shared__ __align__(16) float sB2[64];
    __shared__ float sB3[16];
    __shared__ __align__(16) float sOut[128 * 9];

    float* sH  = sbuf;          // pitch 36
    float* sW2 = sbuf + 4608;   // 64x64

    const int tid = threadIdx.x;

    // ---- phase 1: stage weights ----
    for (int idx = tid; idx < 4096; idx += 256) sW2[idx] = W2[idx];
    for (int idx = tid; idx < 1024; idx += 256) {
        const int k = idx >> 4, c = idx & 15;
        float v = 0.f;
        if (c == 0) v = We[k];
        else if (c < 9) v = Wt[k * 8 + c - 1];
        sW3s[idx] = v;
    }
    if (tid < 64) { sA[tid] = g_A[i * 64 + tid]; sB2[tid] = b2[tid]; }
    if (tid < 16) sB3[tid] = (tid == 0) ? be[0] : (tid < 9 ? bt[tid - 1] : 0.f);
    __syncthreads();

    // ---- GEMM setup: 8 warps as 4(M) x 2(N); thread: 8 rows (stride 4) x 4 cols ----
    const int lane  = tid & 31;
    const int warp  = tid >> 5;
    const int warpM = warp & 3;
    const int warpN = warp >> 2;
    const int mRow0 = warpM * 32 + (lane & 3);     // rows mRow0 + 4*r
    const int nBase = warpN * 32 + (lane >> 2) * 4;

    ull acc[8][2];
#pragma unroll
    for (int r = 0; r < 8; r++) { acc[r][0] = 0ull; acc[r][1] = 0ull; }

    const float4* gB4 = (const float4*)g_B;
    const float4* sA4 = (const float4*)sA;

    for (int kph = 0; kph < 2; kph++) {
        // stage h1 columns [kph*32, kph*32+32)
        for (int idx = tid; idx < 128 * 8; idx += 256) {
            const int m = idx >> 3, kq = idx & 7;
            const int j = jlo + m;
            float4 v = make_float4(0.f, 0.f, 0.f, 0.f);
            if (j < jhi) {
                const float4 b4 = gB4[j * 16 + kph * 8 + kq];
                const float4 a4 = sA4[kph * 8 + kq];
                v.x = fmaxf(a4.x + b4.x, 0.f);
                v.y = fmaxf(a4.y + b4.y, 0.f);
                v.z = fmaxf(a4.z + b4.z, 0.f);
                v.w = fmaxf(a4.w + b4.w, 0.f);
            }
            *(float4*)(sH + m * 36 + kq * 4) = v;
        }
        __syncthreads();

        const float* sHrow = sH + mRow0 * 36;
        const float* w2p   = sW2 + kph * 32 * 64 + nBase;
#pragma unroll
        for (int kg = 0; kg < 8; kg++) {
            // W2 for this k-group: 4 rows of 4 cols each (two ulls = LDS.128)
            ull b0[2], b1v[2], b2v[2], b3[2];
            {
                const ull* bp0 = (const ull*)(w2p + (kg * 4 + 0) * 64);
                const ull* bp1 = (const ull*)(w2p + (kg * 4 + 1) * 64);
                const ull* bp2 = (const ull*)(w2p + (kg * 4 + 2) * 64);
                const ull* bp3 = (const ull*)(w2p + (kg * 4 + 3) * 64);
                b0[0] = bp0[0]; b0[1] = bp0[1];
                b1v[0] = bp1[0]; b1v[1] = bp1[1];
                b2v[0] = bp2[0]; b2v[1] = bp2[1];
                b3[0] = bp3[0]; b3[1] = bp3[1];
            }
#pragma unroll
            for (int r = 0; r < 8; r++) {
                const float4 a4 = *(const float4*)(sHrow + r * 4 * 36 + kg * 4);
                const ull a0 = pack2(a4.x, a4.x);
                const ull a1 = pack2(a4.y, a4.y);
                const ull a2 = pack2(a4.z, a4.z);
                const ull a3 = pack2(a4.w, a4.w);
                ffma2(acc[r][0], a0, b0[0]);  ffma2(acc[r][1], a0, b0[1]);
                ffma2(acc[r][0], a1, b1v[0]); ffma2(acc[r][1], a1, b1v[1]);
                ffma2(acc[r][0], a2, b2v[0]); ffma2(acc[r][1], a2, b2v[1]);
                ffma2(acc[r][0], a3, b3[0]);  ffma2(acc[r][1], a3, b3[1]);
            }
        }
        __syncthreads();
    }

    // ---- h2 = relu(acc + b2) -> h2buf (pitch 68, overlays sH+sW2) ----
    float* h2buf = sbuf;
    const float4 bb = *(const float4*)(sB2 + nBase);
#pragma unroll
    for (int r = 0; r < 8; r++) {
        float x0, x1, x2, x3;
        unpack2(acc[r][0], x0, x1);
        unpack2(acc[r][1], x2, x3);
        float4 h;
        h.x = fmaxf(x0 + bb.x, 0.f);
        h.y = fmaxf(x1 + bb.y, 0.f);
        h.z = fmaxf(x2 + bb.z, 0.f);
        h.w = fmaxf(x3 + bb.w, 0.f);
        *(float4*)(h2buf + (mRow0 + r * 4) * 68 + nBase) = h;
    }
    __syncthreads();

    // ---- heads: 2 threads per row, K split 32/32, f32x2 ----
    {
        const int row = tid >> 1, half = tid & 1;
        const float* hrow = h2buf + row * 68 + half * 32;
        const ull* w3b = (const ull*)sW3s + half * 32 * 8;  // pitch 8 ull
        ull a9[5] = {0ull, 0ull, 0ull, 0ull, 0ull};
#pragma unroll 8
        for (int kk = 0; kk < 32; kk++) {
            const float v = hrow[kk];
            const ull vd = pack2(v, v);
            const ull* wr = w3b + kk * 8;
            ffma2(a9[0], vd, wr[0]);
            ffma2(a9[1], vd, wr[1]);
            ffma2(a9[2], vd, wr[2]);
            ffma2(a9[3], vd, wr[3]);
            ffma2(a9[4], vd, wr[4]);
        }
#pragma unroll
        for (int p = 0; p < 5; p++) {
            ull o = __shfl_xor_sync(0xffffffffu, a9[p], 1);
            fadd2(a9[p], o);
        }
        if (half == 0) {
            float v0, v1, v2, v3, v4, v5, v6, v7, v8, v9;
            unpack2(a9[0], v0, v1); unpack2(a9[1], v2, v3);
            unpack2(a9[2], v4, v5); unpack2(a9[3], v6, v7);
            unpack2(a9[4], v8, v9);
            float* dst = sOut + row * 9;
            dst[0] = v0 + sB3[0]; dst[1] = v1 + sB3[1]; dst[2] = v2 + sB3[2];
            dst[3] = v3 + sB3[3]; dst[4] = v4 + sB3[4]; dst[5] = v5 + sB3[5];
            dst[6] = v6 + sB3[6]; dst[7] = v7 + sB3[7]; dst[8] = v8 + sB3[8];
        }
    }
    __syncthreads();

    // ---- packed-triu contiguous store ----
    const size_t pair0 = (size_t)i * (2 * NN - i - 1) / 2 + (size_t)(jlo - i - 1);
    float* gdst = out + pair0 * 9;
    const int tot = cnt * 9;
    for (int idx = tid; idx < tot; idx += 256) gdst[idx] = sOut[idx];
}

extern "C" void kernel_launch(void* const* d_in, const int* in_sizes, int n_in,
                              void* d_out, int out_size) {
    (void)in_sizes; (void)n_in; (void)out_size;
    const float* X  = (const float*)d_in[0];
    const float* W1 = (const float*)d_in[1];
    const float* b1 = (const float*)d_in[2];
    const float* W2 = (const float*)d_in[3];
    const float* b2 = (const float*)d_in[4];
    const float* We = (const float*)d_in[5];
    const float* be = (const float*)d_in[6];
    const float* Wt = (const float*)d_in[7];
    const float* bt = (const float*)d_in[8];
    float* out = (float*)d_out;

    precompute_kernel<<<NN, DD>>>(X, W1, b1);

    dim3 grid(NN / 128, NN);
    edge_main<<<grid, 256>>>(W2, b2, We, be, Wt, bt, out);
}

// round 4
// speedup vs baseline: 1.4851x; 1.4718x over previous
#include <cuda_runtime.h>
#include <cuda_bf16.h>
#include <cstdint>

#define NN 2048
#define DD 64

typedef unsigned long long ull;

// ---------------- device scratch ----------------
__device__ float g_A[NN * DD];                       // A[i] = x_i @ W1[:64] + b1
__device__ float g_B[NN * DD];                       // B[j] = x_j @ W1[64:]
__device__ __align__(16) unsigned short g_W2Th[64 * 72];  // W2^T hi, [n][k] pitch 72
__device__ __align__(16) unsigned short g_W2Tl[64 * 72];  // W2^T lo
__device__ __align__(16) float g_W3[64 * 12];             // [k][c]: c0=We, c1..8=Wt

// ---------------- helpers ----------------
__device__ __forceinline__ uint32_t smem_u32(const void* p) {
    uint32_t a;
    asm("{ .reg .u64 t; cvta.to.shared.u64 t, %1; cvt.u32.u64 %0, t; }" : "=r"(a) : "l"(p));
    return a;
}
__device__ __forceinline__ ull pack2(float lo, float hi) {
    ull r; asm("mov.b64 %0, {%1, %2};" : "=l"(r) : "f"(lo), "f"(hi)); return r;
}
__device__ __forceinline__ void unpack2(ull v, float& lo, float& hi) {
    asm("mov.b64 {%0, %1}, %2;" : "=f"(lo), "=f"(hi) : "l"(v));
}
__device__ __forceinline__ void ffma2(ull& d, ull a, ull b) {
    asm("fma.rn.f32x2 %0, %1, %2, %0;" : "+l"(d) : "l"(a), "l"(b));
}
__device__ __forceinline__ void fadd2(ull& d, ull a) {
    asm("add.rn.f32x2 %0, %0, %1;" : "+l"(d) : "l"(a));
}

#define LDSM_X4(r0, r1, r2, r3, addr) \
    asm volatile("ldmatrix.sync.aligned.m8n8.x4.shared.b16 {%0,%1,%2,%3}, [%4];" \
        : "=r"(r0), "=r"(r1), "=r"(r2), "=r"(r3) : "r"(addr))
#define LDSM_X2(r0, r1, addr) \
    asm volatile("ldmatrix.sync.aligned.m8n8.x2.shared.b16 {%0,%1}, [%2];" \
        : "=r"(r0), "=r"(r1) : "r"(addr))

__device__ __forceinline__ void mma_bf16(float* c, uint32_t a0, uint32_t a1,
                                         uint32_t a2, uint32_t a3,
                                         uint32_t b0, uint32_t b1) {
    asm volatile(
        "mma.sync.aligned.m16n8k16.row.col.f32.bf16.bf16.f32 "
        "{%0,%1,%2,%3}, {%4,%5,%6,%7}, {%8,%9}, {%0,%1,%2,%3};"
        : "+f"(c[0]), "+f"(c[1]), "+f"(c[2]), "+f"(c[3])
        : "r"(a0), "r"(a1), "r"(a2), "r"(a3), "r"(b0), "r"(b1));
}

// ---------------- Kernel 1: precompute A and B rows ----------------
__global__ void precompute_kernel(const float* __restrict__ X,
                                  const float* __restrict__ W1,
                                  const float* __restrict__ b1) {
    __shared__ float xs[DD];
    const int i = blockIdx.x;
    const int d = threadIdx.x;
    xs[d] = X[i * DD + d];
    __syncthreads();
    float a = b1[d], b = 0.f;
#pragma unroll 8
    for (int k = 0; k < DD; k++) {
        const float xv = xs[k];
        a = fmaf(xv, __ldg(&W1[k * DD + d]), a);
        b = fmaf(xv, __ldg(&W1[(DD + k) * DD + d]), b);
    }
    g_A[i * DD + d] = a;
    g_B[i * DD + d] = b;
}

// ---------------- Kernel 1b: prep W2^T hi/lo (padded pitch 72) + W3 ----------------
__global__ void prep_weights(const float* __restrict__ W2,
                             const float* __restrict__ We,
                             const float* __restrict__ Wt) {
    const int tid = threadIdx.x;
    for (int idx = tid; idx < 64 * 72; idx += 256) {
        const int n = idx / 72, k = idx % 72;
        float v = (k < 64) ? W2[k * 64 + n] : 0.f;
        __nv_bfloat16 h = __float2bfloat16_rn(v);
        float r = v - __bfloat162float(h);
        g_W2Th[idx] = __bfloat16_as_ushort(h);
        g_W2Tl[idx] = __bfloat16_as_ushort(__float2bfloat16_rn(r));
    }
    for (int idx = tid; idx < 768; idx += 256) {
        const int k = idx / 12, c = idx % 12;
        float v = 0.f;
        if (c == 0) v = We[k];
        else if (c < 9) v = Wt[k * 8 + c - 1];
        g_W3[idx] = v;
    }
}

// ---------------- Kernel 2: main pair kernel (mma.sync bf16 3-pass) ----------------
__global__ __launch_bounds__(256) void edge_main(
    const float* __restrict__ b2,
    const float* __restrict__ be, const float* __restrict__ bt,
    float* __restrict__ out)
{
    // static SMEM: 36864 + 3072 + 4608 + 256 + 256 + 64 = 45120 B
    __shared__ __align__(16) char sAB[36864];   // Abuf[128][72]bf16 | BH[64][72] | BL[64][72]
    __shared__ __align__(16) float sW3[768];    // [k][12]
    __shared__ __align__(16) float sOut[1152];  // 128 x 9
    __shared__ __align__(16) float sB2[64];
    __shared__ __align__(16) float sAi[64];
    __shared__ float sB3[16];

    unsigned short* Abuf = (unsigned short*)sAB;            // pitch 72
    unsigned short* BH   = (unsigned short*)(sAB + 18432);  // pitch 72
    unsigned short* BL   = (unsigned short*)(sAB + 27648);
    float* h2 = (float*)sAB;                                // overlay [128][68]

    const int i  = blockIdx.y;
    const int jt = blockIdx.x;
    int jlo = jt * 128; if (i + 1 > jlo) jlo = i + 1;
    int jhi = jt * 128 + 128; if (jhi > NN) jhi = NN;
    if (jlo >= jhi) return;
    const int cnt = jhi - jlo;

    const int tid  = threadIdx.x;
    const int warp = tid >> 5;
    const int lane = tid & 31;

    // ---- stage weights ----
    {
        const int4* srcH = (const int4*)g_W2Th;
        const int4* srcL = (const int4*)g_W2Tl;
        int4* dstH = (int4*)BH;
        int4* dstL = (int4*)BL;
        for (int idx = tid; idx < 576; idx += 256) { dstH[idx] = srcH[idx]; dstL[idx] = srcL[idx]; }
        for (int idx = tid; idx < 768; idx += 256) sW3[idx] = g_W3[idx];
        if (tid < 64) { sB2[tid] = b2[tid]; sAi[tid] = g_A[i * 64 + tid]; }
        if (tid < 16) sB3[tid] = (tid == 0) ? be[0] : (tid < 9 ? bt[tid - 1] : 0.f);
    }
    __syncthreads();

    const float4* gB4 = (const float4*)g_B;
    const float4* sA4 = (const float4*)sAi;

    // ---- stage A-hi: h1 = relu(A[i]+B[j]), bf16 hi ----
    for (int idx = tid; idx < 2048; idx += 256) {
        const int m = idx >> 4, kq = idx & 15;
        const int j = jlo + m;
        float4 v = make_float4(0.f, 0.f, 0.f, 0.f);
        if (j < jhi) {
            const float4 b4 = gB4[j * 16 + kq];
            const float4 a4 = sA4[kq];
            v.x = fmaxf(a4.x + b4.x, 0.f);
            v.y = fmaxf(a4.y + b4.y, 0.f);
            v.z = fmaxf(a4.z + b4.z, 0.f);
            v.w = fmaxf(a4.w + b4.w, 0.f);
        }
        ushort4 hp;
        hp.x = __bfloat16_as_ushort(__float2bfloat16_rn(v.x));
        hp.y = __bfloat16_as_ushort(__float2bfloat16_rn(v.y));
        hp.z = __bfloat16_as_ushort(__float2bfloat16_rn(v.z));
        hp.w = __bfloat16_as_ushort(__float2bfloat16_rn(v.w));
        *(ushort4*)(Abuf + m * 72 + kq * 4) = hp;
    }
    __syncthreads();

    // ---- GEMM ----
    const int m0 = warp * 16;
    float acc[8][4];
#pragma unroll
    for (int nt = 0; nt < 8; nt++)
#pragma unroll
        for (int c = 0; c < 4; c++) acc[nt][c] = 0.f;

    const uint32_t abase  = smem_u32(Abuf);
    const uint32_t bhbase = smem_u32(BH);
    const uint32_t blbase = smem_u32(BL);
    const uint32_t arow_off = (uint32_t)(m0 + (lane & 15)) * 144 + ((lane >> 4) * 8) * 2;
    const uint32_t brow_off = (uint32_t)(lane & 7) * 144 + (((lane >> 3) & 1) * 8) * 2;

    // passes 1-2: A_hi x (B_hi, B_lo)
#pragma unroll
    for (int kt = 0; kt < 4; kt++) {
        uint32_t a0, a1, a2, a3;
        LDSM_X4(a0, a1, a2, a3, abase + arow_off + kt * 32);
#pragma unroll
        for (int nt = 0; nt < 8; nt++) {
            const uint32_t off = brow_off + (uint32_t)nt * 8 * 144 + kt * 32;
            uint32_t bh0, bh1, bl0, bl1;
            LDSM_X2(bh0, bh1, bhbase + off);
            LDSM_X2(bl0, bl1, blbase + off);
            mma_bf16(acc[nt], a0, a1, a2, a3, bh0, bh1);
            mma_bf16(acc[nt], a0, a1, a2, a3, bl0, bl1);
        }
    }
    __syncthreads();

    // ---- restage A-lo in place ----
    for (int idx = tid; idx < 2048; idx += 256) {
        const int m = idx >> 4, kq = idx & 15;
        const int j = jlo + m;
        float4 v = make_float4(0.f, 0.f, 0.f, 0.f);
        if (j < jhi) {
            const float4 b4 = gB4[j * 16 + kq];
            const float4 a4 = sA4[kq];
            v.x = fmaxf(a4.x + b4.x, 0.f);
            v.y = fmaxf(a4.y + b4.y, 0.f);
            v.z = fmaxf(a4.z + b4.z, 0.f);
            v.w = fmaxf(a4.w + b4.w, 0.f);
        }
        ushort4 lp;
        lp.x = __bfloat16_as_ushort(__float2bfloat16_rn(v.x - __bfloat162float(__float2bfloat16_rn(v.x))));
        lp.y = __bfloat16_as_ushort(__float2bfloat16_rn(v.y - __bfloat162float(__float2bfloat16_rn(v.y))));
        lp.z = __bfloat16_as_ushort(__float2bfloat16_rn(v.z - __bfloat162float(__float2bfloat16_rn(v.z))));
        lp.w = __bfloat16_as_ushort(__float2bfloat16_rn(v.w - __bfloat162float(__float2bfloat16_rn(v.w))));
        *(ushort4*)(Abuf + m * 72 + kq * 4) = lp;
    }
    __syncthreads();

    // pass 3: A_lo x B_hi
#pragma unroll
    for (int kt = 0; kt < 4; kt++) {
        uint32_t a0, a1, a2, a3;
        LDSM_X4(a0, a1, a2, a3, abase + arow_off + kt * 32);
#pragma unroll
        for (int nt = 0; nt < 8; nt++) {
            const uint32_t off = brow_off + (uint32_t)nt * 8 * 144 + kt * 32;
            uint32_t bh0, bh1;
            LDSM_X2(bh0, bh1, bhbase + off);
            mma_bf16(acc[nt], a0, a1, a2, a3, bh0, bh1);
        }
    }
    __syncthreads();

    // ---- epilogue: h2 = relu(acc + b2) -> smem overlay (pitch 68) ----
    {
        const int r0 = m0 + (lane >> 2);
        const int cb = (lane & 3) * 2;
#pragma unroll
        for (int nt = 0; nt < 8; nt++) {
            const int n = nt * 8 + cb;
            float2 p0, p1;
            p0.x = fmaxf(acc[nt][0] + sB2[n], 0.f);
            p0.y = fmaxf(acc[nt][1] + sB2[n + 1], 0.f);
            p1.x = fmaxf(acc[nt][2] + sB2[n], 0.f);
            p1.y = fmaxf(acc[nt][3] + sB2[n + 1], 0.f);
            *(float2*)(h2 + r0 * 68 + n) = p0;
            *(float2*)(h2 + (r0 + 8) * 68 + n) = p1;
        }
    }
    __syncthreads();

    // ---- heads: 2 threads per row, K split 32/32, f32x2 ----
    {
        const int row = tid >> 1, half = tid & 1;
        const float* hrow = h2 + row * 68 + half * 32;
        const char* w3b = (const char*)sW3 + (size_t)half * 32 * 48;
        ull a9[5] = {0ull, 0ull, 0ull, 0ull, 0ull};
#pragma unroll 8
        for (int kk = 0; kk < 32; kk++) {
            const char* wr = w3b + kk * 48;
            const longlong2 w01 = *(const longlong2*)(wr);
            const longlong2 w23 = *(const longlong2*)(wr + 16);
            const ull w4 = *(const ull*)(wr + 32);
            const ull vd = pack2(hrow[kk], hrow[kk]);
            ffma2(a9[0], vd, (ull)w01.x);
            ffma2(a9[1], vd, (ull)w01.y);
            ffma2(a9[2], vd, (ull)w23.x);
            ffma2(a9[3], vd, (ull)w23.y);
            ffma2(a9[4], vd, w4);
        }
#pragma unroll
        for (int p = 0; p < 5; p++) {
            ull o = __shfl_xor_sync(0xffffffffu, a9[p], 1);
            fadd2(a9[p], o);
        }
        if (half == 0) {
            float v[10];
            unpack2(a9[0], v[0], v[1]); unpack2(a9[1], v[2], v[3]);
            unpack2(a9[2], v[4], v[5]); unpack2(a9[3], v[6], v[7]);
            unpack2(a9[4], v[8], v[9]);
            float* dst = sOut + row * 9;
#pragma unroll
            for (int c = 0; c < 9; c++) dst[c] = v[c] + sB3[c];
        }
    }
    __syncthreads();

    // ---- packed-triu contiguous store ----
    const size_t pair0 = (size_t)i * (2 * NN - i - 1) / 2 + (size_t)(jlo - i - 1);
    float* gdst = out + pair0 * 9;
    const int tot = cnt * 9;
    for (int idx = tid; idx < tot; idx += 256) gdst[idx] = sOut[idx];
}

extern "C" void kernel_launch(void* const* d_in, const int* in_sizes, int n_in,
                              void* d_out, int out_size) {
    (void)in_sizes; (void)n_in; (void)out_size;
    const float* X  = (const float*)d_in[0];
    const float* W1 = (const float*)d_in[1];
    const float* b1 = (const float*)d_in[2];
    const float* W2 = (const float*)d_in[3];
    const float* b2 = (const float*)d_in[4];
    const float* We = (const float*)d_in[5];
    const float* be = (const float*)d_in[6];
    const float* Wt = (const float*)d_in[7];
    const float* bt = (const float*)d_in[8];
    float* out = (float*)d_out;

    precompute_kernel<<<NN, DD>>>(X, W1, b1);
    prep_weights<<<1, 256>>>(W2, We, Wt);

    dim3 grid(NN / 128, NN);
    edge_main<<<grid, 256>>>(b2, be, bt, out);
}

// round 5
// speedup vs baseline: 2.4936x; 1.6791x over previous
#include <cuda_runtime.h>
#include <cuda_bf16.h>
#include <cstdint>

#define NN 2048
#define DD 64

typedef unsigned long long ull;

// ---------------- device scratch ----------------
__device__ float g_A[NN * DD];                       // A[i] = x_i @ W1[:64] + b1
__device__ float g_B[NN * DD];                       // B[j] = x_j @ W1[64:]
__device__ __align__(16) unsigned short g_W2Th[64 * 72];  // W2^T hi, [n][k] pitch 72
__device__ __align__(16) unsigned short g_W2Tl[64 * 72];  // W2^T lo
__device__ __align__(16) unsigned short g_W3Th[16 * 72];  // W3^T hi, [n=16][k] pitch 72
__device__ __align__(16) unsigned short g_W3Tl[16 * 72];  // W3^T lo

// ---------------- helpers ----------------
__device__ __forceinline__ uint32_t smem_u32(const void* p) {
    uint32_t a;
    asm("{ .reg .u64 t; cvta.to.shared.u64 t, %1; cvt.u32.u64 %0, t; }" : "=r"(a) : "l"(p));
    return a;
}
__device__ __forceinline__ uint32_t packbf(float hi, float lo) {
    uint32_t r; asm("cvt.rn.bf16x2.f32 %0, %1, %2;" : "=r"(r) : "f"(hi), "f"(lo)); return r;
}
__device__ __forceinline__ float resid(float v) {
    return v - __uint_as_float(__float_as_uint(v) & 0xFFFF0000u);
}

#define LDSM_X4(r0, r1, r2, r3, addr) \
    asm volatile("ldmatrix.sync.aligned.m8n8.x4.shared.b16 {%0,%1,%2,%3}, [%4];" \
        : "=r"(r0), "=r"(r1), "=r"(r2), "=r"(r3) : "r"(addr))
#define LDSM_X2(r0, r1, addr) \
    asm volatile("ldmatrix.sync.aligned.m8n8.x2.shared.b16 {%0,%1}, [%2];" \
        : "=r"(r0), "=r"(r1) : "r"(addr))

__device__ __forceinline__ void mma_bf16(float* c, uint32_t a0, uint32_t a1,
                                         uint32_t a2, uint32_t a3,
                                         uint32_t b0, uint32_t b1) {
    asm volatile(
        "mma.sync.aligned.m16n8k16.row.col.f32.bf16.bf16.f32 "
        "{%0,%1,%2,%3}, {%4,%5,%6,%7}, {%8,%9}, {%0,%1,%2,%3};"
        : "+f"(c[0]), "+f"(c[1]), "+f"(c[2]), "+f"(c[3])
        : "r"(a0), "r"(a1), "r"(a2), "r"(a3), "r"(b0), "r"(b1));
}

// ---------------- Kernel 1: precompute A and B rows ----------------
__global__ void precompute_kernel(const float* __restrict__ X,
                                  const float* __restrict__ W1,
                                  const float* __restrict__ b1) {
    __shared__ float xs[DD];
    const int i = blockIdx.x;
    const int d = threadIdx.x;
    xs[d] = X[i * DD + d];
    __syncthreads();
    float a = b1[d], b = 0.f;
#pragma unroll 8
    for (int k = 0; k < DD; k++) {
        const float xv = xs[k];
        a = fmaf(xv, __ldg(&W1[k * DD + d]), a);
        b = fmaf(xv, __ldg(&W1[(DD + k) * DD + d]), b);
    }
    g_A[i * DD + d] = a;
    g_B[i * DD + d] = b;
}

// ---------------- Kernel 1b: prep W2^T / W3^T hi-lo tiles ----------------
__global__ void prep_weights(const float* __restrict__ W2,
                             const float* __restrict__ We,
                             const float* __restrict__ Wt) {
    const int tid = threadIdx.x;
    for (int idx = tid; idx < 64 * 72; idx += 256) {
        const int n = idx / 72, k = idx % 72;
        float v = (k < 64) ? W2[k * 64 + n] : 0.f;
        __nv_bfloat16 h = __float2bfloat16_rn(v);
        g_W2Th[idx] = __bfloat16_as_ushort(h);
        g_W2Tl[idx] = __bfloat16_as_ushort(__float2bfloat16_rn(v - __bfloat162float(h)));
    }
    for (int idx = tid; idx < 16 * 72; idx += 256) {
        const int n = idx / 72, k = idx % 72;
        float v = 0.f;
        if (k < 64) {
            if (n == 0) v = We[k];
            else if (n < 9) v = Wt[k * 8 + n - 1];
        }
        __nv_bfloat16 h = __float2bfloat16_rn(v);
        g_W3Th[idx] = __bfloat16_as_ushort(h);
        g_W3Tl[idx] = __bfloat16_as_ushort(__float2bfloat16_rn(v - __bfloat162float(h)));
    }
}

// ---------------- Kernel 2: main pair kernel ----------------
__global__ __launch_bounds__(256) void edge_main(
    const float* __restrict__ b2,
    const float* __restrict__ be, const float* __restrict__ bt,
    float* __restrict__ out)
{
    __shared__ __align__(16) char sAB[36864];        // Abuf[128][72] | BH[64][72] | BL[64][72]
    __shared__ __align__(16) unsigned short sW3T[2 * 16 * 72];  // hi | lo
    __shared__ __align__(16) float sOut[1152];       // 128 x 9
    __shared__ __align__(16) float sB2[64];
    __shared__ __align__(16) float sAi[64];
    __shared__ float sB3[16];

    unsigned short* Abuf = (unsigned short*)sAB;            // pitch 72
    unsigned short* BH   = (unsigned short*)(sAB + 18432);  // pitch 72
    unsigned short* BL   = (unsigned short*)(sAB + 27648);

    const int i  = blockIdx.y;
    const int jt = blockIdx.x;
    int jlo = jt * 128; if (i + 1 > jlo) jlo = i + 1;
    int jhi = jt * 128 + 128; if (jhi > NN) jhi = NN;
    if (jlo >= jhi) return;
    const int cnt = jhi - jlo;

    const int tid  = threadIdx.x;
    const int warp = tid >> 5;
    const int lane = tid & 31;

    // ---- stage weights ----
    {
        const int4* srcH = (const int4*)g_W2Th;
        const int4* srcL = (const int4*)g_W2Tl;
        int4* dstH = (int4*)BH;
        int4* dstL = (int4*)BL;
        for (int idx = tid; idx < 576; idx += 256) { dstH[idx] = srcH[idx]; dstL[idx] = srcL[idx]; }
        if (tid < 144) {
            ((int4*)sW3T)[tid] = ((const int4*)g_W3Th)[tid];
            ((int4*)(sW3T + 1152))[tid] = ((const int4*)g_W3Tl)[tid];
        }
        if (tid < 64) { sB2[tid] = b2[tid]; sAi[tid] = g_A[i * 64 + tid]; }
        if (tid < 16) sB3[tid] = (tid == 0) ? be[0] : (tid < 9 ? bt[tid - 1] : 0.f);
    }

    const float4* gB4 = (const float4*)g_B;

    // ---- stage A-hi (prmt truncation), keep A-lo residuals in registers ----
    uint2 aloR[8];
    {
        // sAi written above by threads <64; need it visible — cheap sync here
        __syncthreads();
        const float4* sA4 = (const float4*)sAi;
#pragma unroll
        for (int it = 0; it < 8; it++) {
            const int idx = tid + it * 256;
            const int m = idx >> 4, kq = idx & 15;
            const int j = jlo + m;
            float4 v = make_float4(0.f, 0.f, 0.f, 0.f);
            if (j < jhi) {
                const float4 b4 = gB4[j * 16 + kq];
                const float4 a4 = sA4[kq];
                v.x = fmaxf(a4.x + b4.x, 0.f);
                v.y = fmaxf(a4.y + b4.y, 0.f);
                v.z = fmaxf(a4.z + b4.z, 0.f);
                v.w = fmaxf(a4.w + b4.w, 0.f);
            }
            uint2 hp;
            hp.x = __byte_perm(__float_as_uint(v.x), __float_as_uint(v.y), 0x7632);
            hp.y = __byte_perm(__float_as_uint(v.z), __float_as_uint(v.w), 0x7632);
            aloR[it].x = packbf(resid(v.y), resid(v.x));
            aloR[it].y = packbf(resid(v.w), resid(v.z));
            *(uint2*)(Abuf + m * 72 + kq * 4) = hp;
        }
    }
    __syncthreads();

    // ---- GEMM ----
    const int m0 = warp * 16;
    float acc[8][4];
#pragma unroll
    for (int nt = 0; nt < 8; nt++)
#pragma unroll
        for (int c = 0; c < 4; c++) acc[nt][c] = 0.f;

    const uint32_t abase  = smem_u32(Abuf);
    const uint32_t bhbase = smem_u32(BH);
    const uint32_t blbase = smem_u32(BL);
    const uint32_t arow_off = (uint32_t)(m0 + (lane & 15)) * 144 + ((lane >> 4) * 8) * 2;
    const uint32_t brow_off = (uint32_t)(lane & 7) * 144 + (((lane >> 3) & 1) * 8) * 2;

    // passes 1-2: A_hi x (B_hi, B_lo)
#pragma unroll
    for (int kt = 0; kt < 4; kt++) {
        uint32_t a0, a1, a2, a3;
        LDSM_X4(a0, a1, a2, a3, abase + arow_off + kt * 32);
#pragma unroll
        for (int nt = 0; nt < 8; nt++) {
            const uint32_t off = brow_off + (uint32_t)nt * 8 * 144 + kt * 32;
            uint32_t bh0, bh1, bl0, bl1;
            LDSM_X2(bh0, bh1, bhbase + off);
            LDSM_X2(bl0, bl1, blbase + off);
            mma_bf16(acc[nt], a0, a1, a2, a3, bh0, bh1);
            mma_bf16(acc[nt], a0, a1, a2, a3, bl0, bl1);
        }
    }
    __syncthreads();

    // ---- restage A-lo from registers (no global reload) ----
#pragma unroll
    for (int it = 0; it < 8; it++) {
        const int idx = tid + it * 256;
        const int m = idx >> 4, kq = idx & 15;
        *(uint2*)(Abuf + m * 72 + kq * 4) = aloR[it];
    }
    __syncthreads();

    // pass 3: A_lo x B_hi
#pragma unroll
    for (int kt = 0; kt < 4; kt++) {
        uint32_t a0, a1, a2, a3;
        LDSM_X4(a0, a1, a2, a3, abase + arow_off + kt * 32);
#pragma unroll
        for (int nt = 0; nt < 8; nt++) {
            const uint32_t off = brow_off + (uint32_t)nt * 8 * 144 + kt * 32;
            uint32_t bh0, bh1;
            LDSM_X2(bh0, bh1, bhbase + off);
            mma_bf16(acc[nt], a0, a1, a2, a3, bh0, bh1);
        }
    }

    // ---- heads: relu+bias in regs, C->A fragment refeed, 3-pass vs W3 hi/lo ----
    {
        const int tg = lane & 3;
        float oacc[2][4];
#pragma unroll
        for (int no = 0; no < 2; no++)
#pragma unroll
            for (int c = 0; c < 4; c++) oacc[no][c] = 0.f;

        const uint32_t w3b = smem_u32(sW3T);
        const uint32_t w3row = (uint32_t)(lane & 7) * 144 + (((lane >> 3) & 1) * 8) * 2;

#pragma unroll
        for (int kt = 0; kt < 4; kt++) {
            const float2 bA = *(const float2*)(sB2 + (2 * kt) * 8 + tg * 2);
            const float2 bB = *(const float2*)(sB2 + (2 * kt + 1) * 8 + tg * 2);
            const float va0 = fmaxf(acc[2 * kt][0] + bA.x, 0.f);
            const float va1 = fmaxf(acc[2 * kt][1] + bA.y, 0.f);
            const float va2 = fmaxf(acc[2 * kt][2] + bA.x, 0.f);
            const float va3 = fmaxf(acc[2 * kt][3] + bA.y, 0.f);
            const float vb0 = fmaxf(acc[2 * kt + 1][0] + bB.x, 0.f);
            const float vb1 = fmaxf(acc[2 * kt + 1][1] + bB.y, 0.f);
            const float vb2 = fmaxf(acc[2 * kt + 1][2] + bB.x, 0.f);
            const float vb3 = fmaxf(acc[2 * kt + 1][3] + bB.y, 0.f);
            const uint32_t a0 = __byte_perm(__float_as_uint(va0), __float_as_uint(va1), 0x7632);
            const uint32_t a1 = __byte_perm(__float_as_uint(va2), __float_as_uint(va3), 0x7632);
            const uint32_t a2 = __byte_perm(__float_as_uint(vb0), __float_as_uint(vb1), 0x7632);
            const uint32_t a3 = __byte_perm(__float_as_uint(vb2), __float_as_uint(vb3), 0x7632);
            const uint32_t la0 = packbf(resid(va1), resid(va0));
            const uint32_t la1 = packbf(resid(va3), resid(va2));
            const uint32_t la2 = packbf(resid(vb1), resid(vb0));
            const uint32_t la3 = packbf(resid(vb3), resid(vb2));
#pragma unroll
            for (int no = 0; no < 2; no++) {
                const uint32_t addr = w3b + (uint32_t)no * 8 * 144 + w3row + kt * 32;
                uint32_t bh0, bh1, bl0, bl1;
                LDSM_X2(bh0, bh1, addr);
                LDSM_X2(bl0, bl1, addr + 2304);
                mma_bf16(oacc[no], a0, a1, a2, a3, bh0, bh1);
                mma_bf16(oacc[no], a0, a1, a2, a3, bl0, bl1);
                mma_bf16(oacc[no], la0, la1, la2, la3, bh0, bh1);
            }
        }

        // store to sOut (pitch 9): cols 0-7 from tile 0, col 8 from tile 1
        const int r0 = m0 + (lane >> 2);
        const int r1 = r0 + 8;
        const int c0 = tg * 2;
        sOut[r0 * 9 + c0]     = oacc[0][0] + sB3[c0];
        sOut[r0 * 9 + c0 + 1] = oacc[0][1] + sB3[c0 + 1];
        sOut[r1 * 9 + c0]     = oacc[0][2] + sB3[c0];
        sOut[r1 * 9 + c0 + 1] = oacc[0][3] + sB3[c0 + 1];
        if (tg == 0) {
            sOut[r0 * 9 + 8] = oacc[1][0] + sB3[8];
            sOut[r1 * 9 + 8] = oacc[1][2] + sB3[8];
        }
    }
    __syncthreads();

    // ---- packed-triu contiguous store ----
    const size_t pair0 = (size_t)i * (2 * NN - i - 1) / 2 + (size_t)(jlo - i - 1);
    float* gdst = out + pair0 * 9;
    const int tot = cnt * 9;
    for (int idx = tid; idx < tot; idx += 256) gdst[idx] = sOut[idx];
}

extern "C" void kernel_launch(void* const* d_in, const int* in_sizes, int n_in,
                              void* d_out, int out_size) {
    (void)in_sizes; (void)n_in; (void)out_size;
    const float* X  = (const float*)d_in[0];
    const float* W1 = (const float*)d_in[1];
    const float* b1 = (const float*)d_in[2];
    const float* W2 = (const float*)d_in[3];
    const float* b2 = (const float*)d_in[4];
    const float* We = (const float*)d_in[5];
    const float* be = (const float*)d_in[6];
    const float* Wt = (const float*)d_in[7];
    const float* bt = (const float*)d_in[8];
    float* out = (float*)d_out;

    precompute_kernel<<<NN, DD>>>(X, W1, b1);
    prep_weights<<<1, 256>>>(W2, We, Wt);

    dim3 grid(NN / 128, NN);
    edge_main<<<grid, 256>>>(b2, be, bt, out);
}

// round 6
// speedup vs baseline: 2.9448x; 1.1810x over previous
#include <cuda_runtime.h>
#include <cuda_bf16.h>
#include <cstdint>

#define NN 2048
#define DD 64

// ---------------- device scratch ----------------
__device__ float g_A[NN * DD];                       // A[i] = x_i @ W1[:64] + b1
__device__ float g_B[NN * DD];                       // B[j] = x_j @ W1[64:]
__device__ __align__(16) unsigned short g_W2Th[64 * 72];  // W2^T hi, [n][k] pitch 72
__device__ __align__(16) unsigned short g_W2Tl[64 * 72];  // W2^T lo
__device__ __align__(16) unsigned short g_W3Th[16 * 72];  // W3^T hi
__device__ __align__(16) unsigned short g_W3Tl[16 * 72];  // W3^T lo

// ---------------- helpers ----------------
__device__ __forceinline__ uint32_t smem_u32(const void* p) {
    uint32_t a;
    asm("{ .reg .u64 t; cvta.to.shared.u64 t, %1; cvt.u32.u64 %0, t; }" : "=r"(a) : "l"(p));
    return a;
}
__device__ __forceinline__ uint32_t packbf(float hi, float lo) {
    uint32_t r; asm("cvt.rn.bf16x2.f32 %0, %1, %2;" : "=r"(r) : "f"(hi), "f"(lo)); return r;
}
__device__ __forceinline__ float resid(float v) {
    return v - __uint_as_float(__float_as_uint(v) & 0xFFFF0000u);
}

#define LDSM_X4(r0, r1, r2, r3, addr) \
    asm volatile("ldmatrix.sync.aligned.m8n8.x4.shared.b16 {%0,%1,%2,%3}, [%4];" \
        : "=r"(r0), "=r"(r1), "=r"(r2), "=r"(r3) : "r"(addr))

__device__ __forceinline__ void mma_bf16(float* c, uint32_t a0, uint32_t a1,
                                         uint32_t a2, uint32_t a3,
                                         uint32_t b0, uint32_t b1) {
    asm volatile(
        "mma.sync.aligned.m16n8k16.row.col.f32.bf16.bf16.f32 "
        "{%0,%1,%2,%3}, {%4,%5,%6,%7}, {%8,%9}, {%0,%1,%2,%3};"
        : "+f"(c[0]), "+f"(c[1]), "+f"(c[2]), "+f"(c[3])
        : "r"(a0), "r"(a1), "r"(a2), "r"(a3), "r"(b0), "r"(b1));
}

// ---------------- Kernel 1: precompute A/B rows + weight tiles ----------------
__global__ void precompute_kernel(const float* __restrict__ X,
                                  const float* __restrict__ W1,
                                  const float* __restrict__ b1,
                                  const float* __restrict__ W2,
                                  const float* __restrict__ We,
                                  const float* __restrict__ Wt) {
    if (blockIdx.x < NN) {
        __shared__ float xs[DD];
        const int i = blockIdx.x;
        const int d = threadIdx.x;
        xs[d] = X[i * DD + d];
        __syncthreads();
        float a = b1[d], b = 0.f;
#pragma unroll 8
        for (int k = 0; k < DD; k++) {
            const float xv = xs[k];
            a = fmaf(xv, __ldg(&W1[k * DD + d]), a);
            b = fmaf(xv, __ldg(&W1[(DD + k) * DD + d]), b);
        }
        g_A[i * DD + d] = a;
        g_B[i * DD + d] = b;
    } else {
        const int t = threadIdx.x;
        for (int idx = t; idx < 64 * 72; idx += 64) {
            const int n = idx / 72, k = idx % 72;
            float v = (k < 64) ? W2[k * 64 + n] : 0.f;
            __nv_bfloat16 h = __float2bfloat16_rn(v);
            g_W2Th[idx] = __bfloat16_as_ushort(h);
            g_W2Tl[idx] = __bfloat16_as_ushort(__float2bfloat16_rn(v - __bfloat162float(h)));
        }
        for (int idx = t; idx < 16 * 72; idx += 64) {
            const int n = idx / 72, k = idx % 72;
            float v = 0.f;
            if (k < 64) {
                if (n == 0) v = We[k];
                else if (n < 9) v = Wt[k * 8 + n - 1];
            }
            __nv_bfloat16 h = __float2bfloat16_rn(v);
            g_W3Th[idx] = __bfloat16_as_ushort(h);
            g_W3Tl[idx] = __bfloat16_as_ushort(__float2bfloat16_rn(v - __bfloat162float(h)));
        }
    }
}

// ---------------- SMEM layout (dynamic, 65088 B) ----------------
// Ah   [128][72] bf16   @ 0       (18432)
// Al   [128][72] bf16   @ 18432   (18432)
// BH   [64][72]  bf16   @ 36864   (9216)
// BL   [64][72]  bf16   @ 46080   (9216)   (BH + 9216, contiguous for lane trick)
// W3hi [16][72]  bf16   @ 55296   (2304)
// W3lo [16][72]  bf16   @ 57600   (2304)
// sOut [128][9]  f32    @ 59904   (4608)
// sB2  [64]      f32    @ 64512   (256)
// sB3  [16]      f32    @ 64768   (64)
#define SMEM_BYTES 65088

// ---------------- Kernel 2: main pair kernel ----------------
__global__ __launch_bounds__(256, 2) void edge_main(
    const float* __restrict__ b2,
    const float* __restrict__ be, const float* __restrict__ bt,
    float* __restrict__ out)
{
    extern __shared__ __align__(16) char smem[];
    unsigned short* Ah = (unsigned short*)smem;
    unsigned short* Al = (unsigned short*)(smem + 18432);
    unsigned short* BH = (unsigned short*)(smem + 36864);
    unsigned short* W3 = (unsigned short*)(smem + 55296);
    float* sOut = (float*)(smem + 59904);
    float* sB2  = (float*)(smem + 64512);
    float* sB3  = (float*)(smem + 64768);

    const int i  = blockIdx.y;
    const int jt = blockIdx.x;
    int jlo = jt * 128; if (i + 1 > jlo) jlo = i + 1;
    int jhi = jt * 128 + 128; if (jhi > NN) jhi = NN;
    if (jlo >= jhi) return;
    const int cnt = jhi - jlo;

    const int tid  = threadIdx.x;
    const int warp = tid >> 5;
    const int lane = tid & 31;

    // ---- stage weights ----
    {
        const int4* srcH = (const int4*)g_W2Th;
        const int4* srcL = (const int4*)g_W2Tl;
        int4* dstB = (int4*)BH;
        for (int idx = tid; idx < 576; idx += 256) {
            dstB[idx] = srcH[idx];
            dstB[idx + 576] = srcL[idx];
        }
        if (tid < 144) {
            ((int4*)W3)[tid]       = ((const int4*)g_W3Th)[tid];
            ((int4*)W3)[tid + 144] = ((const int4*)g_W3Tl)[tid];
        }
        if (tid < 64) sB2[tid] = b2[tid];
        if (tid < 16) sB3[tid] = (tid == 0) ? be[0] : (tid < 9 ? bt[tid - 1] : 0.f);
    }

    // ---- stage Ah + Al in one pass (h1 = relu(A[i]+B[j])) ----
    {
        const float4* gB4 = (const float4*)g_B;
        const float4* gA4 = (const float4*)g_A;
#pragma unroll
        for (int it = 0; it < 8; it++) {
            const int idx = tid + it * 256;
            const int m = idx >> 4, kq = idx & 15;
            const int j = jlo + m;
            float4 v = make_float4(0.f, 0.f, 0.f, 0.f);
            if (j < jhi) {
                const float4 b4 = gB4[j * 16 + kq];
                const float4 a4 = __ldg(&gA4[i * 16 + kq]);
                v.x = fmaxf(a4.x + b4.x, 0.f);
                v.y = fmaxf(a4.y + b4.y, 0.f);
                v.z = fmaxf(a4.z + b4.z, 0.f);
                v.w = fmaxf(a4.w + b4.w, 0.f);
            }
            uint2 hp, lp;
            hp.x = __byte_perm(__float_as_uint(v.x), __float_as_uint(v.y), 0x7632);
            hp.y = __byte_perm(__float_as_uint(v.z), __float_as_uint(v.w), 0x7632);
            lp.x = packbf(resid(v.y), resid(v.x));
            lp.y = packbf(resid(v.w), resid(v.z));
            *(uint2*)(Ah + m * 72 + kq * 4) = hp;
            *(uint2*)(Al + m * 72 + kq * 4) = lp;
        }
    }
    __syncthreads();

    // ---- fused 3-pass GEMM: acc += Ah*Bh + Ah*Bl + Al*Bh ----
    float acc[8][4];
#pragma unroll
    for (int nt = 0; nt < 8; nt++)
#pragma unroll
        for (int c = 0; c < 4; c++) acc[nt][c] = 0.f;

    const uint32_t aoff   = (uint32_t)(warp * 16 + (lane & 15)) * 144 + (lane >> 4) * 16;
    const uint32_t ahbase = smem_u32(Ah) + aoff;
    const uint32_t albase = ahbase + 18432;
    // per-lane combined hi/lo B address: lanes 0-15 -> BH, 16-31 -> BL
    const uint32_t bbase = smem_u32(BH) + ((lane >= 16) ? 9216u : 0u)
                         + (uint32_t)(lane & 7) * 144 + ((lane >> 3) & 1) * 16;
    const uint32_t w3base = smem_u32(W3) + ((lane >= 16) ? 2304u : 0u)
                          + (uint32_t)(lane & 7) * 144 + ((lane >> 3) & 1) * 16;

#pragma unroll
    for (int kt = 0; kt < 4; kt++) {
        uint32_t ah0, ah1, ah2, ah3, al0, al1, al2, al3;
        LDSM_X4(ah0, ah1, ah2, ah3, ahbase + kt * 32);
        LDSM_X4(al0, al1, al2, al3, albase + kt * 32);
#pragma unroll
        for (int nt = 0; nt < 8; nt++) {
            uint32_t bh0, bh1, bl0, bl1;
            LDSM_X4(bh0, bh1, bl0, bl1, bbase + (uint32_t)nt * 1152 + kt * 32);
            mma_bf16(acc[nt], ah0, ah1, ah2, ah3, bh0, bh1);
            mma_bf16(acc[nt], ah0, ah1, ah2, ah3, bl0, bl1);
            mma_bf16(acc[nt], al0, al1, al2, al3, bh0, bh1);
        }
    }

    // ---- heads: relu+bias in regs, C->A fragment refeed, 3-pass vs W3 hi/lo ----
    {
        const int tg = lane & 3;
        float oacc[2][4];
#pragma unroll
        for (int no = 0; no < 2; no++)
#pragma unroll
            for (int c = 0; c < 4; c++) oacc[no][c] = 0.f;

#pragma unroll
        for (int kt = 0; kt < 4; kt++) {
            const float2 bA = *(const float2*)(sB2 + (2 * kt) * 8 + tg * 2);
            const float2 bB = *(const float2*)(sB2 + (2 * kt + 1) * 8 + tg * 2);
            const float va0 = fmaxf(acc[2 * kt][0] + bA.x, 0.f);
            const float va1 = fmaxf(acc[2 * kt][1] + bA.y, 0.f);
            const float va2 = fmaxf(acc[2 * kt][2] + bA.x, 0.f);
            const float va3 = fmaxf(acc[2 * kt][3] + bA.y, 0.f);
            const float vb0 = fmaxf(acc[2 * kt + 1][0] + bB.x, 0.f);
            const float vb1 = fmaxf(acc[2 * kt + 1][1] + bB.y, 0.f);
            const float vb2 = fmaxf(acc[2 * kt + 1][2] + bB.x, 0.f);
            const float vb3 = fmaxf(acc[2 * kt + 1][3] + bB.y, 0.f);
            const uint32_t a0 = __byte_perm(__float_as_uint(va0), __float_as_uint(va1), 0x7632);
            const uint32_t a1 = __byte_perm(__float_as_uint(va2), __float_as_uint(va3), 0x7632);
            const uint32_t a2 = __byte_perm(__float_as_uint(vb0), __float_as_uint(vb1), 0x7632);
            const uint32_t a3 = __byte_perm(__float_as_uint(vb2), __float_as_uint(vb3), 0x7632);
            const uint32_t la0 = packbf(resid(va1), resid(va0));
            const uint32_t la1 = packbf(resid(va3), resid(va2));
            const uint32_t la2 = packbf(resid(vb1), resid(vb0));
            const uint32_t la3 = packbf(resid(vb3), resid(vb2));
#pragma unroll
            for (int no = 0; no < 2; no++) {
                uint32_t bh0, bh1, bl0, bl1;
                LDSM_X4(bh0, bh1, bl0, bl1, w3base + (uint32_t)no * 1152 + kt * 32);
                mma_bf16(oacc[no], a0, a1, a2, a3, bh0, bh1);
                mma_bf16(oacc[no], a0, a1, a2, a3, bl0, bl1);
                mma_bf16(oacc[no], la0, la1, la2, la3, bh0, bh1);
            }
        }

        // store to sOut (pitch 9): cols 0-7 from tile 0, col 8 from tile 1
        const int r0 = warp * 16 + (lane >> 2);
        const int r1 = r0 + 8;
        const int c0 = tg * 2;
        sOut[r0 * 9 + c0]     = oacc[0][0] + sB3[c0];
        sOut[r0 * 9 + c0 + 1] = oacc[0][1] + sB3[c0 + 1];
        sOut[r1 * 9 + c0]     = oacc[0][2] + sB3[c0];
        sOut[r1 * 9 + c0 + 1] = oacc[0][3] + sB3[c0 + 1];
        if (tg == 0) {
            sOut[r0 * 9 + 8] = oacc[1][0] + sB3[8];
            sOut[r1 * 9 + 8] = oacc[1][2] + sB3[8];
        }
    }
    __syncthreads();

    // ---- packed-triu contiguous store ----
    const size_t pair0 = (size_t)i * (2 * NN - i - 1) / 2 + (size_t)(jlo - i - 1);
    float* gdst = out + pair0 * 9;
    const int tot = cnt * 9;
    for (int idx = tid; idx < tot; idx += 256) gdst[idx] = sOut[idx];
}

extern "C" void kernel_launch(void* const* d_in, const int* in_sizes, int n_in,
                              void* d_out, int out_size) {
    (void)in_sizes; (void)n_in; (void)out_size;
    const float* X  = (const float*)d_in[0];
    const float* W1 = (const float*)d_in[1];
    const float* b1 = (const float*)d_in[2];
    const float* W2 = (const float*)d_in[3];
    const float* b2 = (const float*)d_in[4];
    const float* We = (const float*)d_in[5];
    const float* be = (const float*)d_in[6];
    const float* Wt = (const float*)d_in[7];
    const float* bt = (const float*)d_in[8];
    float* out = (float*)d_out;

    cudaFuncSetAttribute(edge_main, cudaFuncAttributeMaxDynamicSharedMemorySize, SMEM_BYTES);

    precompute_kernel<<<NN + 1, DD>>>(X, W1, b1, W2, We, Wt);

    dim3 grid(NN / 128, NN);
    edge_main<<<grid, 256, SMEM_BYTES>>>(b2, be, bt, out);
}